// round 1
// baseline (speedup 1.0000x reference)
#include <cuda_runtime.h>
#include <math.h>

// Problem constants (fixed by the reference config)
#define Mm 8
#define Bb 4096
#define Tt 33
#define Dd 8
#define FFf 28
#define Rr 3
#define NP 4          // (m,b) pairs per block
#define TPB 160       // 4*33 = 132 active threads, padded to 5 warps
#define EPSf 1e-5f
#define ATT_SCALE 0.3535533905932738f  // 1/sqrt(8)
#define INV_SQRT2 0.7071067811865476f

__device__ __forceinline__ float dot8(const float* __restrict__ a,
                                      const float* __restrict__ w) {
    // w points into shared memory, 16B-aligned rows of 8 floats
    float4 w0 = *reinterpret_cast<const float4*>(w);
    float4 w1 = *reinterpret_cast<const float4*>(w + 4);
    float acc = a[0] * w0.x;
    acc = fmaf(a[1], w0.y, acc);
    acc = fmaf(a[2], w0.z, acc);
    acc = fmaf(a[3], w0.w, acc);
    acc = fmaf(a[4], w1.x, acc);
    acc = fmaf(a[5], w1.y, acc);
    acc = fmaf(a[6], w1.z, acc);
    acc = fmaf(a[7], w1.w, acc);
    return acc;
}

__global__ __launch_bounds__(TPB)
void fused_block_kernel(
    const float* __restrict__ gx,
    const float* __restrict__ gln1w, const float* __restrict__ gln1b,
    const float* __restrict__ gqkvw, const float* __restrict__ gprojw,
    const float* __restrict__ gln2w, const float* __restrict__ gln2b,
    const float* __restrict__ gfc1A, const float* __restrict__ gfc1B,
    const float* __restrict__ gfc1Wf,
    const float* __restrict__ gfc2A, const float* __restrict__ gfc2B,
    const float* __restrict__ gfc2Wf,
    float* __restrict__ gout)
{
    // Per-model weights (transposed so each output column is a contiguous
    // 8-float row -> two LDS.128 per dot product, broadcast across the pair).
    __shared__ __align__(16) float s_qkvT[24][Dd];   // [out col][in]  (q:0-7 k:8-15 v:16-23)
    __shared__ __align__(16) float s_projT[Dd][Dd];
    __shared__ __align__(16) float s_w1T[FFf][Dd];   // fc1_A@fc1_B + fc1_Wf, transposed
    __shared__ __align__(16) float s_w2T[Dd][FFf];   // fc2_A@fc2_B + fc2_Wf, transposed
    __shared__ __align__(16) float s_ln[4][Dd];      // ln1w, ln1b, ln2w, ln2b
    __shared__ __align__(16) float s_k[NP][Tt][Dd];
    __shared__ __align__(16) float s_v[NP][Tt][Dd];
    __shared__ float s_sc[NP][Tt][Tt];               // score rows (each row touched by 1 thread)

    const int tid = threadIdx.x;
    const int m  = blockIdx.x / (Bb / NP);
    const int bc = blockIdx.x % (Bb / NP);

    // ---- cooperative weight staging (collapse low-rank terms once) ----
    for (int idx = tid; idx < Dd * 24; idx += TPB) {
        int i = idx / 24, o = idx % 24;
        s_qkvT[o][i] = gqkvw[(m * Dd + i) * 24 + o];
    }
    for (int idx = tid; idx < Dd * Dd; idx += TPB) {
        int i = idx >> 3, o = idx & 7;
        s_projT[o][i] = gprojw[(m * Dd + i) * Dd + o];
    }
    for (int idx = tid; idx < Dd * FFf; idx += TPB) {
        int i = idx / FFf, o = idx % FFf;
        float acc = gfc1Wf[(m * Dd + i) * FFf + o];
        #pragma unroll
        for (int r = 0; r < Rr; r++)
            acc = fmaf(gfc1A[(m * Dd + i) * Rr + r],
                       gfc1B[(m * Rr + r) * FFf + o], acc);
        s_w1T[o][i] = acc;
    }
    for (int idx = tid; idx < FFf * Dd; idx += TPB) {
        int f = idx >> 3, o = idx & 7;
        float acc = gfc2Wf[(m * FFf + f) * Dd + o];
        #pragma unroll
        for (int r = 0; r < Rr; r++)
            acc = fmaf(gfc2A[(m * FFf + f) * Rr + r],
                       gfc2B[(m * Rr + r) * Dd + o], acc);
        s_w2T[o][f] = acc;
    }
    if (tid < Dd) {
        s_ln[0][tid] = gln1w[m * Dd + tid];
        s_ln[1][tid] = gln1b[m * Dd + tid];
        s_ln[2][tid] = gln2w[m * Dd + tid];
        s_ln[3][tid] = gln2b[m * Dd + tid];
    }
    __syncthreads();

    const bool active = (tid < NP * Tt);
    const int p = tid / Tt;
    const int t = tid - p * Tt;
    const int b = bc * NP + p;

    float xr[8];       // residual stream (registers, never re-read from HBM)
    float q[8];
    long base = ((((long)m * Bb + b) * Tt) + t) * Dd;

    if (active) {
        float4 a0 = *reinterpret_cast<const float4*>(gx + base);
        float4 a1 = *reinterpret_cast<const float4*>(gx + base + 4);
        xr[0] = a0.x; xr[1] = a0.y; xr[2] = a0.z; xr[3] = a0.w;
        xr[4] = a1.x; xr[5] = a1.y; xr[6] = a1.z; xr[7] = a1.w;

        // LayerNorm 1
        float mean = 0.f;
        #pragma unroll
        for (int i = 0; i < 8; i++) mean += xr[i];
        mean *= 0.125f;
        float var = 0.f;
        #pragma unroll
        for (int i = 0; i < 8; i++) { float d = xr[i] - mean; var = fmaf(d, d, var); }
        var *= 0.125f;
        float rstd = rsqrtf(var + EPSf);
        float h[8];
        #pragma unroll
        for (int i = 0; i < 8; i++)
            h[i] = fmaf((xr[i] - mean) * rstd, s_ln[0][i], s_ln[1][i]);

        // qkv projection; q stays in regs, k/v go to shared for the pair
        #pragma unroll
        for (int o = 0; o < 8; o++) q[o] = dot8(h, &s_qkvT[o][0]);
        #pragma unroll
        for (int o = 0; o < 8; o++) s_k[p][t][o] = dot8(h, &s_qkvT[8 + o][0]);
        #pragma unroll
        for (int o = 0; o < 8; o++) s_v[p][t][o] = dot8(h, &s_qkvT[16 + o][0]);
    }
    __syncthreads();

    if (active) {
        // ---- causal attention, row t (keys 0..t) ----
        float mx = -1e30f;
        for (int j = 0; j <= t; j++) {
            float d = dot8(q, &s_k[p][j][0]) * ATT_SCALE;
            s_sc[p][t][j] = d;
            mx = fmaxf(mx, d);
        }
        float y[8] = {0.f, 0.f, 0.f, 0.f, 0.f, 0.f, 0.f, 0.f};
        float sum = 0.f;
        for (int j = 0; j <= t; j++) {
            float e = __expf(s_sc[p][t][j] - mx);
            sum += e;
            const float* vj = &s_v[p][j][0];
            float4 v0 = *reinterpret_cast<const float4*>(vj);
            float4 v1 = *reinterpret_cast<const float4*>(vj + 4);
            y[0] = fmaf(e, v0.x, y[0]); y[1] = fmaf(e, v0.y, y[1]);
            y[2] = fmaf(e, v0.z, y[2]); y[3] = fmaf(e, v0.w, y[3]);
            y[4] = fmaf(e, v1.x, y[4]); y[5] = fmaf(e, v1.y, y[5]);
            y[6] = fmaf(e, v1.z, y[6]); y[7] = fmaf(e, v1.w, y[7]);
        }
        float inv = 1.f / sum;
        #pragma unroll
        for (int i = 0; i < 8; i++) y[i] *= inv;

        // output projection + residual
        #pragma unroll
        for (int o = 0; o < 8; o++) xr[o] += dot8(y, &s_projT[o][0]);

        // LayerNorm 2
        float mean = 0.f;
        #pragma unroll
        for (int i = 0; i < 8; i++) mean += xr[i];
        mean *= 0.125f;
        float var = 0.f;
        #pragma unroll
        for (int i = 0; i < 8; i++) { float d = xr[i] - mean; var = fmaf(d, d, var); }
        var *= 0.125f;
        float rstd = rsqrtf(var + EPSf);
        float h2[8];
        #pragma unroll
        for (int i = 0; i < 8; i++)
            h2[i] = fmaf((xr[i] - mean) * rstd, s_ln[2][i], s_ln[3][i]);

        // fc1 (collapsed weights) + exact-erf GELU
        float g[FFf];
        #pragma unroll
        for (int o = 0; o < FFf; o++) {
            float u = dot8(h2, &s_w1T[o][0]);
            g[o] = 0.5f * u * (1.f + erff(u * INV_SQRT2));
        }

        // fc2 (collapsed weights) + residual
        #pragma unroll
        for (int o = 0; o < 8; o++) {
            const float* w = &s_w2T[o][0];
            float acc = 0.f;
            #pragma unroll
            for (int f = 0; f < FFf; f += 4) {
                float4 w4 = *reinterpret_cast<const float4*>(w + f);
                acc = fmaf(g[f],     w4.x, acc);
                acc = fmaf(g[f + 1], w4.y, acc);
                acc = fmaf(g[f + 2], w4.z, acc);
                acc = fmaf(g[f + 3], w4.w, acc);
            }
            xr[o] += acc;
        }

        float4 r0 = make_float4(xr[0], xr[1], xr[2], xr[3]);
        float4 r1 = make_float4(xr[4], xr[5], xr[6], xr[7]);
        *reinterpret_cast<float4*>(gout + base)     = r0;
        *reinterpret_cast<float4*>(gout + base + 4) = r1;
    }
}

extern "C" void kernel_launch(void* const* d_in, const int* in_sizes, int n_in,
                              void* d_out, int out_size) {
    (void)in_sizes; (void)n_in; (void)out_size;
    const float* x      = (const float*)d_in[0];
    const float* ln1w   = (const float*)d_in[1];
    const float* ln1b   = (const float*)d_in[2];
    const float* qkvw   = (const float*)d_in[3];
    const float* projw  = (const float*)d_in[4];
    const float* ln2w   = (const float*)d_in[5];
    const float* ln2b   = (const float*)d_in[6];
    const float* fc1A   = (const float*)d_in[7];
    const float* fc1B   = (const float*)d_in[8];
    const float* fc1Wf  = (const float*)d_in[9];
    const float* fc2A   = (const float*)d_in[10];
    const float* fc2B   = (const float*)d_in[11];
    const float* fc2Wf  = (const float*)d_in[12];
    float* out = (float*)d_out;

    dim3 grid(Mm * (Bb / NP));
    dim3 block(TPB);
    fused_block_kernel<<<grid, block>>>(
        x, ln1w, ln1b, qkvw, projw, ln2w, ln2b,
        fc1A, fc1B, fc1Wf, fc2A, fc2B, fc2Wf, out);
}